// round 1
// baseline (speedup 1.0000x reference)
#include <cuda_runtime.h>

// PlaneValidator: per (batch,plane) symmetric-chamfer between 1024 points and
// their plane-reflections, then per-batch conf ranking + angular NMS.
//
// Shapes: sample_points (4,1024,3) f32, y_pred (4,16,4) f32, sde_threshold scalar.
// Output: (4,16,8) f32 rows = [n_hat(3), point(3), conf, sde], NMS-ranked, zeroed when dropped.

#define NB 4
#define NPTS 1024
#define NH 16
#define THREADS 256
#define ROWS_PER_BLOCK 512      // 2 rows per thread

#define COS_THR 0.8660254037844387f

__device__ float g_sde[NB * NH];

__global__ void zero_sde_kernel() {
    if (threadIdx.x < NB * NH) g_sde[threadIdx.x] = 0.0f;
}

// grid.x = 64 (b,h) * 4 sub-blocks.
// sub = blockIdx.x & 3 : bit1 = pass (0: rows=points vs refl cols; 1: rows=refl vs point cols)
//                        bit0 = row chunk (0..1, 512 rows each)
__global__ __launch_bounds__(THREADS) void chamfer_kernel(
        const float* __restrict__ pts, const float* __restrict__ ypred) {
    const int bid  = blockIdx.x;
    const int bh   = bid >> 2;
    const int sub  = bid & 3;
    const int pass = sub >> 1;
    const int rc   = sub & 1;
    const int t    = threadIdx.x;

    // Plane parameters (broadcast loads, redundant per thread — trivial)
    const float* yp = ypred + bh * 4;
    const float nx = yp[0], ny = yp[1], nz = yp[2], dpl = yp[3];
    const float inv = 1.0f / sqrtf(nx * nx + ny * ny + nz * nz);
    const float nhx = nx * inv, nhy = ny * inv, nhz = nz * inv;
    const float dh  = dpl * inv;

    const float* pb = pts + (bh >> 4) * (NPTS * 3);

    // Stage the "column" set in shared as float4 (LDS.128, warp-broadcast reads)
    __shared__ float4 sB[NPTS];
    for (int i = t; i < NPTS; i += THREADS) {
        float px = pb[i * 3 + 0], py = pb[i * 3 + 1], pz = pb[i * 3 + 2];
        if (pass == 0) {  // columns are reflections
            float proj = fmaf(px, nhx, fmaf(py, nhy, fmaf(pz, nhz, dh)));
            float s = -2.0f * proj;
            px = fmaf(s, nhx, px);
            py = fmaf(s, nhy, py);
            pz = fmaf(s, nhz, pz);
        }
        sB[i] = make_float4(px, py, pz, 0.0f);
    }

    // This thread's 2 rows, in registers
    float ax[2], ay[2], az[2];
#pragma unroll
    for (int k = 0; k < 2; k++) {
        int r = rc * ROWS_PER_BLOCK + k * THREADS + t;
        float px = pb[r * 3 + 0], py = pb[r * 3 + 1], pz = pb[r * 3 + 2];
        if (pass == 1) {  // rows are reflections
            float proj = fmaf(px, nhx, fmaf(py, nhy, fmaf(pz, nhz, dh)));
            float s = -2.0f * proj;
            px = fmaf(s, nhx, px);
            py = fmaf(s, nhy, py);
            pz = fmaf(s, nhz, pz);
        }
        ax[k] = px; ay[k] = py; az[k] = pz;
    }
    __syncthreads();

    float best0 = 3.4e38f, best1 = 3.4e38f;
#pragma unroll 8
    for (int m = 0; m < NPTS; m++) {
        float4 q = sB[m];
        float dx0 = ax[0] - q.x, dy0 = ay[0] - q.y, dz0 = az[0] - q.z;
        float d0 = fmaf(dx0, dx0, fmaf(dy0, dy0, dz0 * dz0));
        best0 = fminf(best0, d0);
        float dx1 = ax[1] - q.x, dy1 = ay[1] - q.y, dz1 = az[1] - q.z;
        float d1 = fmaf(dx1, dx1, fmaf(dy1, dy1, dz1 * dz1));
        best1 = fminf(best1, d1);
    }
    float acc = best0 + best1;  // sum of this thread's two row-mins

    // Block reduction of row-min sum
#pragma unroll
    for (int o = 16; o > 0; o >>= 1)
        acc += __shfl_down_sync(0xFFFFFFFFu, acc, o);

    __shared__ float wsum[THREADS / 32];
    if ((t & 31) == 0) wsum[t >> 5] = acc;
    __syncthreads();
    if (t == 0) {
        float s = 0.0f;
#pragma unroll
        for (int i = 0; i < THREADS / 32; i++) s += wsum[i];
        atomicAdd(&g_sde[bh], s * (1.0f / (float)NPTS));
    }
}

// One block per batch; serial per-batch logic on thread 0 (H=16, trivial).
__global__ void finalize_kernel(const float* __restrict__ ypred,
                                const int* __restrict__ thr_ptr,
                                float* __restrict__ out) {
    const int b = blockIdx.x;
    if (threadIdx.x != 0) return;

    // Threshold: decode int32 vs float32 bit pattern defensively
    int tv = thr_ptr[0];
    float tf = __int_as_float(tv);
    float thr = (tf >= 1e-6f && tf <= 1e9f) ? tf : (float)tv;

    float nhv[NH][3], ptv[NH][3], sd[NH], cf[NH];
    float mn = 3.4e38f, mx = -3.4e38f;
    for (int h = 0; h < NH; h++) {
        const float* yp = ypred + (b * NH + h) * 4;
        float nx = yp[0], ny = yp[1], nz = yp[2], d = yp[3];
        float inv = 1.0f / sqrtf(nx * nx + ny * ny + nz * nz);
        float nhx = nx * inv, nhy = ny * inv, nhz = nz * inv;
        float dh = d * inv;
        nhv[h][0] = nhx; nhv[h][1] = nhy; nhv[h][2] = nhz;
        ptv[h][0] = -dh * nhx; ptv[h][1] = -dh * nhy; ptv[h][2] = -dh * nhz;
        sd[h] = g_sde[b * NH + h];
        mn = fminf(mn, sd[h]);
        mx = fmaxf(mx, sd[h]);
    }
    for (int h = 0; h < NH; h++)
        cf[h] = 1.0f - (sd[h] - mn) / (mx - mn);

    // Stable insertion sort: conf descending (== jnp.argsort(-cf), stable)
    int ord[NH];
    for (int i = 0; i < NH; i++) ord[i] = i;
    for (int i = 1; i < NH; i++) {
        int k = ord[i];
        float ck = cf[k];
        int j = i - 1;
        while (j >= 0 && cf[ord[j]] < ck) { ord[j + 1] = ord[j]; j--; }
        ord[j + 1] = k;
    }

    // valid + sequential NMS (exact fori_loop semantics: live keep[i])
    bool keep[NH];
    for (int i = 0; i < NH; i++) keep[i] = (sd[ord[i]] <= thr);
    for (int i = 0; i < NH; i++) {
        if (!keep[i]) continue;
        const float* ni = nhv[ord[i]];
        for (int j = i + 1; j < NH; j++) {
            const float* nj = nhv[ord[j]];
            float dt = ni[0] * nj[0] + ni[1] * nj[1] + ni[2] * nj[2];
            if (dt > COS_THR) keep[j] = false;  // clip to [-1,1] doesn't change this test
        }
    }

    // rank = stable argsort(~keep): kept first, each group in order
    int rank[NH];
    int c = 0;
    for (int i = 0; i < NH; i++) if (keep[i])  rank[c++] = i;
    for (int i = 0; i < NH; i++) if (!keep[i]) rank[c++] = i;

    // Emit all 512/NB floats (output buffer is poisoned; write zeros explicitly)
    for (int i = 0; i < NH; i++) {
        int s = rank[i];          // position in sorted order
        int src = ord[s];         // original plane index
        bool k = keep[s];
        float* o = out + (b * NH + i) * 8;
        o[0] = k ? nhv[src][0] : 0.0f;
        o[1] = k ? nhv[src][1] : 0.0f;
        o[2] = k ? nhv[src][2] : 0.0f;
        o[3] = k ? ptv[src][0] : 0.0f;
        o[4] = k ? ptv[src][1] : 0.0f;
        o[5] = k ? ptv[src][2] : 0.0f;
        o[6] = k ? cf[src]     : 0.0f;
        o[7] = k ? sd[src]     : 0.0f;
    }
}

extern "C" void kernel_launch(void* const* d_in, const int* in_sizes, int n_in,
                              void* d_out, int out_size) {
    // Identify inputs by element count (robust to metadata ordering)
    const float* pts = nullptr;    // 12288 elems
    const float* ypred = nullptr;  // 256 elems
    const int* thr = nullptr;      // 1 elem
    for (int i = 0; i < n_in; i++) {
        if (in_sizes[i] == NB * NPTS * 3)   pts   = (const float*)d_in[i];
        else if (in_sizes[i] == NB * NH * 4) ypred = (const float*)d_in[i];
        else if (in_sizes[i] == 1)           thr   = (const int*)d_in[i];
    }
    float* out = (float*)d_out;

    zero_sde_kernel<<<1, 64>>>();
    chamfer_kernel<<<NB * NH * 4, THREADS>>>(pts, ypred);
    finalize_kernel<<<NB, 32>>>(ypred, thr, out);
}

// round 2
// speedup vs baseline: 1.6812x; 1.6812x over previous
#include <cuda_runtime.h>

// PlaneValidator: symmetric-chamfer between 1024 points and their per-plane
// reflections, then per-batch conf ranking + angular NMS.
//
// Key facts exploited:
//  - D[n,m] = |p_n - r_m|^2 is SYMMETRIC (reflection = involutive isometry),
//    so sde = 2 * mean_n min_m D.  Half the pairs.
//  - min_m (P2[n] + R2[m] - 2 p_n.r_m) = P2[n] + min_m (R2[m] - 2 p_n.r_m):
//    inner loop is 3 FMA + 1 FMNMX per pair using shared float4(-2r, R2).

#define NB 4
#define NPTS 1024
#define NH 16
#define THREADS 256
#define ROW_CHUNK 512           // 2 chunks per (b,h); 2 rows per thread

#define COS_THR 0.8660254037844387f

__device__ float g_part[NB * NH * 2];   // per-block partial sums (no zeroing needed)

__global__ __launch_bounds__(THREADS) void chamfer_kernel(
        const float* __restrict__ pts, const float* __restrict__ ypred) {
    const int bid = blockIdx.x;
    const int bh  = bid >> 1;          // (b,h) pair
    const int rc  = bid & 1;           // row chunk
    const int t   = threadIdx.x;

    // Plane parameters
    const float* yp = ypred + bh * 4;
    const float nx = yp[0], ny = yp[1], nz = yp[2], dpl = yp[3];
    const float inv = 1.0f / sqrtf(nx * nx + ny * ny + nz * nz);
    const float nhx = nx * inv, nhy = ny * inv, nhz = nz * inv;
    const float dh  = dpl * inv;

    const float* pb = pts + (bh >> 4) * (NPTS * 3);

    // Stage columns: reflections as float4(-2rx, -2ry, -2rz, |r|^2)
    __shared__ float4 sB[NPTS];
    for (int i = t; i < NPTS; i += THREADS) {
        float px = pb[i * 3 + 0], py = pb[i * 3 + 1], pz = pb[i * 3 + 2];
        float proj = fmaf(px, nhx, fmaf(py, nhy, fmaf(pz, nhz, dh)));
        float s = -2.0f * proj;
        float rx = fmaf(s, nhx, px);
        float ry = fmaf(s, nhy, py);
        float rz = fmaf(s, nhz, pz);
        float r2 = fmaf(rx, rx, fmaf(ry, ry, rz * rz));
        sB[i] = make_float4(-2.0f * rx, -2.0f * ry, -2.0f * rz, r2);
    }

    // This thread's 2 rows (plain points) + their squared norms
    float ax[2], ay[2], az[2], p2[2];
#pragma unroll
    for (int k = 0; k < 2; k++) {
        int r = rc * ROW_CHUNK + k * THREADS + t;
        float px = pb[r * 3 + 0], py = pb[r * 3 + 1], pz = pb[r * 3 + 2];
        ax[k] = px; ay[k] = py; az[k] = pz;
        p2[k] = fmaf(px, px, fmaf(py, py, pz * pz));
    }
    __syncthreads();

    // Track e_m = R2[m] - 2 p.r_m ; row-min of D = p2 + min e
    float best0 = 3.4e38f, best1 = 3.4e38f;
#pragma unroll 8
    for (int m = 0; m < NPTS; m++) {
        float4 q = sB[m];
        float e0 = fmaf(ax[0], q.x, fmaf(ay[0], q.y, fmaf(az[0], q.z, q.w)));
        best0 = fminf(best0, e0);
        float e1 = fmaf(ax[1], q.x, fmaf(ay[1], q.y, fmaf(az[1], q.z, q.w)));
        best1 = fminf(best1, e1);
    }
    float acc = (best0 + p2[0]) + (best1 + p2[1]);

    // Block reduction of row-min sums
#pragma unroll
    for (int o = 16; o > 0; o >>= 1)
        acc += __shfl_down_sync(0xFFFFFFFFu, acc, o);

    __shared__ float wsum[THREADS / 32];
    if ((t & 31) == 0) wsum[t >> 5] = acc;
    __syncthreads();
    if (t == 0) {
        float s = 0.0f;
#pragma unroll
        for (int i = 0; i < THREADS / 32; i++) s += wsum[i];
        g_part[bid] = s;   // raw sum of 512 row-mins; scaled in finalize
    }
}

// One block per batch; serial per-batch logic on thread 0 (H=16, trivial).
__global__ void finalize_kernel(const float* __restrict__ ypred,
                                const int* __restrict__ thr_ptr,
                                float* __restrict__ out) {
    const int b = blockIdx.x;
    if (threadIdx.x != 0) return;

    // Threshold: decode int32 vs float32 bit pattern defensively
    int tv = thr_ptr[0];
    float tf = __int_as_float(tv);
    float thr = (tf >= 1e-6f && tf <= 1e9f) ? tf : (float)tv;

    float nhv[NH][3], ptv[NH][3], sd[NH], cf[NH];
    float mn = 3.4e38f, mx = -3.4e38f;
    for (int h = 0; h < NH; h++) {
        const float* yp = ypred + (b * NH + h) * 4;
        float nx = yp[0], ny = yp[1], nz = yp[2], d = yp[3];
        float inv = 1.0f / sqrtf(nx * nx + ny * ny + nz * nz);
        float nhx = nx * inv, nhy = ny * inv, nhz = nz * inv;
        float dh = d * inv;
        nhv[h][0] = nhx; nhv[h][1] = nhy; nhv[h][2] = nhz;
        ptv[h][0] = -dh * nhx; ptv[h][1] = -dh * nhy; ptv[h][2] = -dh * nhz;
        int bh = b * NH + h;
        // sde = mean_n min_m + mean_m min_n = 2 * mean(row mins)   (D symmetric)
        sd[h] = (g_part[2 * bh] + g_part[2 * bh + 1]) * (2.0f / (float)NPTS);
        mn = fminf(mn, sd[h]);
        mx = fmaxf(mx, sd[h]);
    }
    for (int h = 0; h < NH; h++)
        cf[h] = 1.0f - (sd[h] - mn) / (mx - mn);

    // Stable insertion sort: conf descending (== jnp.argsort(-cf), stable)
    int ord[NH];
    for (int i = 0; i < NH; i++) ord[i] = i;
    for (int i = 1; i < NH; i++) {
        int k = ord[i];
        float ck = cf[k];
        int j = i - 1;
        while (j >= 0 && cf[ord[j]] < ck) { ord[j + 1] = ord[j]; j--; }
        ord[j + 1] = k;
    }

    // valid + sequential NMS (exact fori_loop semantics: live keep[i])
    bool keep[NH];
    for (int i = 0; i < NH; i++) keep[i] = (sd[ord[i]] <= thr);
    for (int i = 0; i < NH; i++) {
        if (!keep[i]) continue;
        const float* ni = nhv[ord[i]];
        for (int j = i + 1; j < NH; j++) {
            const float* nj = nhv[ord[j]];
            float dt = ni[0] * nj[0] + ni[1] * nj[1] + ni[2] * nj[2];
            if (dt > COS_THR) keep[j] = false;
        }
    }

    // rank = stable argsort(~keep): kept first, each group in order
    int rank[NH];
    int c = 0;
    for (int i = 0; i < NH; i++) if (keep[i])  rank[c++] = i;
    for (int i = 0; i < NH; i++) if (!keep[i]) rank[c++] = i;

    // Emit all floats (output buffer is poisoned; write zeros explicitly)
    for (int i = 0; i < NH; i++) {
        int s = rank[i];
        int src = ord[s];
        bool k = keep[s];
        float* o = out + (b * NH + i) * 8;
        o[0] = k ? nhv[src][0] : 0.0f;
        o[1] = k ? nhv[src][1] : 0.0f;
        o[2] = k ? nhv[src][2] : 0.0f;
        o[3] = k ? ptv[src][0] : 0.0f;
        o[4] = k ? ptv[src][1] : 0.0f;
        o[5] = k ? ptv[src][2] : 0.0f;
        o[6] = k ? cf[src]     : 0.0f;
        o[7] = k ? sd[src]     : 0.0f;
    }
}

extern "C" void kernel_launch(void* const* d_in, const int* in_sizes, int n_in,
                              void* d_out, int out_size) {
    const float* pts = nullptr;    // 12288 elems
    const float* ypred = nullptr;  // 256 elems
    const int* thr = nullptr;      // 1 elem
    for (int i = 0; i < n_in; i++) {
        if (in_sizes[i] == NB * NPTS * 3)    pts   = (const float*)d_in[i];
        else if (in_sizes[i] == NB * NH * 4) ypred = (const float*)d_in[i];
        else if (in_sizes[i] == 1)           thr   = (const int*)d_in[i];
    }
    float* out = (float*)d_out;

    chamfer_kernel<<<NB * NH * 2, THREADS>>>(pts, ypred);
    finalize_kernel<<<NB, 32>>>(ypred, thr, out);
}

// round 3
// speedup vs baseline: 2.4135x; 1.4356x over previous
#include <cuda_runtime.h>

// PlaneValidator: symmetric-chamfer between 1024 points and their per-plane
// reflections, then per-batch conf ranking + angular NMS.  Single fused kernel:
// last-arriving block performs the (warp-parallel) finalization.
//
//  - D[n,m] = |p_n - r_m|^2 is SYMMETRIC (reflection = involutive isometry),
//    so sde = 2 * mean_n min_m D.
//  - min_m (P2[n] + R2[m] - 2 p_n.r_m) = P2[n] + min_m (R2[m] - 2 p_n.r_m):
//    inner loop is 3 FMA + 1 FMNMX per pair using shared float4(-2r, R2).

#define NB 4
#define NPTS 1024
#define NH 16
#define THREADS 256
#define ROW_CHUNK 512           // 2 chunks per (b,h); 2 rows per thread
#define NBLOCKS (NB * NH * 2)   // 128

#define COS_THR 0.8660254037844387f
#define FULL 0xFFFFFFFFu

__device__ float g_part[NBLOCKS];   // per-block partial sums (rewritten every launch)
__device__ int   g_count = 0;       // arrival counter (self-resetting)

__global__ __launch_bounds__(THREADS) void plane_validator_kernel(
        const float* __restrict__ pts, const float* __restrict__ ypred,
        const int* __restrict__ thr_ptr, float* __restrict__ out) {
    const int bid = blockIdx.x;
    const int bh  = bid >> 1;          // (b,h) pair
    const int rc  = bid & 1;           // row chunk
    const int t   = threadIdx.x;

    // ---------------- chamfer phase ----------------
    const float* yp = ypred + bh * 4;
    const float nx = yp[0], ny = yp[1], nz = yp[2], dpl = yp[3];
    const float inv = 1.0f / sqrtf(nx * nx + ny * ny + nz * nz);
    const float nhx = nx * inv, nhy = ny * inv, nhz = nz * inv;
    const float dh  = dpl * inv;

    const float* pb = pts + (bh >> 4) * (NPTS * 3);

    // Stage columns: reflections as float4(-2rx, -2ry, -2rz, |r|^2)
    __shared__ float4 sB[NPTS];
    for (int i = t; i < NPTS; i += THREADS) {
        float px = pb[i * 3 + 0], py = pb[i * 3 + 1], pz = pb[i * 3 + 2];
        float proj = fmaf(px, nhx, fmaf(py, nhy, fmaf(pz, nhz, dh)));
        float s = -2.0f * proj;
        float rx = fmaf(s, nhx, px);
        float ry = fmaf(s, nhy, py);
        float rz = fmaf(s, nhz, pz);
        float r2 = fmaf(rx, rx, fmaf(ry, ry, rz * rz));
        sB[i] = make_float4(-2.0f * rx, -2.0f * ry, -2.0f * rz, r2);
    }

    float ax[2], ay[2], az[2], p2[2];
#pragma unroll
    for (int k = 0; k < 2; k++) {
        int r = rc * ROW_CHUNK + k * THREADS + t;
        float px = pb[r * 3 + 0], py = pb[r * 3 + 1], pz = pb[r * 3 + 2];
        ax[k] = px; ay[k] = py; az[k] = pz;
        p2[k] = fmaf(px, px, fmaf(py, py, pz * pz));
    }
    __syncthreads();

    float best0 = 3.4e38f, best1 = 3.4e38f;
#pragma unroll 8
    for (int m = 0; m < NPTS; m++) {
        float4 q = sB[m];
        float e0 = fmaf(ax[0], q.x, fmaf(ay[0], q.y, fmaf(az[0], q.z, q.w)));
        best0 = fminf(best0, e0);
        float e1 = fmaf(ax[1], q.x, fmaf(ay[1], q.y, fmaf(az[1], q.z, q.w)));
        best1 = fminf(best1, e1);
    }
    float acc = (best0 + p2[0]) + (best1 + p2[1]);

#pragma unroll
    for (int o = 16; o > 0; o >>= 1)
        acc += __shfl_down_sync(FULL, acc, o);

    __shared__ float wsum[THREADS / 32];
    __shared__ int s_last;
    if ((t & 31) == 0) wsum[t >> 5] = acc;
    __syncthreads();
    if (t == 0) {
        float s = 0.0f;
#pragma unroll
        for (int i = 0; i < THREADS / 32; i++) s += wsum[i];
        g_part[bid] = s;                         // raw sum of 512 row-mins
        __threadfence();                         // publish before arrival
        int old = atomicAdd(&g_count, 1);
        s_last = (old == NBLOCKS - 1);
        if (old == NBLOCKS - 1) g_count = 0;     // reset for next graph replay
    }
    __syncthreads();
    if (!s_last) return;

    // ---------------- finalize phase (last block only; lanes 0..63) ----------------
    // lane l: b = l>>4, idx-in-batch = l&15.  16-lane subgroups via shfl width=16.
    __shared__ float s_ex[8][64];   // exchange: nx,ny,nz,px,py,pz,cf,sd by sorted pos

    const int l = t;
    float v_nx = 0, v_ny = 0, v_nz = 0, v_px = 0, v_py = 0, v_pz = 0, v_cf = 0, v_sd = 0;
    int pos = l & 15, b = l >> 4;

    if (l < 64) {
        // threshold: decode int32 vs float32 bit pattern defensively
        int tv = thr_ptr[0];
        float tf = __int_as_float(tv);
        float thr = (tf >= 1e-6f && tf <= 1e9f) ? tf : (float)tv;

        const float* yq = ypred + l * 4;
        float qx = yq[0], qy = yq[1], qz = yq[2], qd = yq[3];
        float qi = 1.0f / sqrtf(qx * qx + qy * qy + qz * qz);
        v_nx = qx * qi; v_ny = qy * qi; v_nz = qz * qi;
        float qdh = qd * qi;
        v_px = -qdh * v_nx; v_py = -qdh * v_ny; v_pz = -qdh * v_nz;

        // sde = 2 * mean(row mins): combine the two chunk partials (volatile: other blocks wrote)
        volatile float* gp = g_part;
        v_sd = (gp[2 * l] + gp[2 * l + 1]) * (2.0f / (float)NPTS);

        // group min/max over 16 lanes
        float mn = v_sd, mx = v_sd;
#pragma unroll
        for (int o = 8; o > 0; o >>= 1) {
            mn = fminf(mn, __shfl_xor_sync(FULL, mn, o, 16));
            mx = fmaxf(mx, __shfl_xor_sync(FULL, mx, o, 16));
        }
        v_cf = 1.0f - (v_sd - mn) / (mx - mn);

        // stable descending rank (== stable argsort(-cf))
        int rank = 0;
#pragma unroll
        for (int j = 0; j < NH; j++) {
            float cfj = __shfl_sync(FULL, v_cf, j, 16);
            rank += (cfj > v_cf) || (cfj == v_cf && j < pos);
        }
        int slot = b * NH + rank;
        s_ex[0][slot] = v_nx; s_ex[1][slot] = v_ny; s_ex[2][slot] = v_nz;
        s_ex[3][slot] = v_px; s_ex[4][slot] = v_py; s_ex[5][slot] = v_pz;
        s_ex[6][slot] = v_cf; s_ex[7][slot] = v_sd;
        // stash thr across the barrier in a register each lane already has
        v_cf = thr;  // temporarily reuse; restored from shared below
    }
    __syncthreads();
    if (l >= 64) return;

    float thr = v_cf;
    v_nx = s_ex[0][l]; v_ny = s_ex[1][l]; v_nz = s_ex[2][l];
    v_px = s_ex[3][l]; v_py = s_ex[4][l]; v_pz = s_ex[5][l];
    v_cf = s_ex[6][l]; v_sd = s_ex[7][l];

    // sequential NMS over sorted positions, live keep bits
    int keep = (v_sd <= thr);
#pragma unroll
    for (int i = 0; i < NH; i++) {
        int   ki  = __shfl_sync(FULL, keep, i, 16);
        float inx = __shfl_sync(FULL, v_nx, i, 16);
        float iny = __shfl_sync(FULL, v_ny, i, 16);
        float inz = __shfl_sync(FULL, v_nz, i, 16);
        float dt = inx * v_nx + iny * v_ny + inz * v_nz;
        if (ki && pos > i && dt > COS_THR) keep = 0;
    }

    // stable partition destination: kept first (in order), dropped after (in order)
    unsigned ball = __ballot_sync(FULL, keep);
    unsigned seg = (ball >> (l & 16)) & 0xFFFFu;       // this 16-lane group's bits
    int kept_before = __popc(seg & ((1u << pos) - 1));
    int total_kept  = __popc(seg);
    int dest = keep ? kept_before : total_kept + (pos - kept_before);

    float* o = out + (b * NH + dest) * 8;
    float4 r0 = keep ? make_float4(v_nx, v_ny, v_nz, v_px) : make_float4(0, 0, 0, 0);
    float4 r1 = keep ? make_float4(v_py, v_pz, v_cf, v_sd) : make_float4(0, 0, 0, 0);
    ((float4*)o)[0] = r0;
    ((float4*)o)[1] = r1;
}

extern "C" void kernel_launch(void* const* d_in, const int* in_sizes, int n_in,
                              void* d_out, int out_size) {
    const float* pts = nullptr;    // 12288 elems
    const float* ypred = nullptr;  // 256 elems
    const int* thr = nullptr;      // 1 elem
    for (int i = 0; i < n_in; i++) {
        if (in_sizes[i] == NB * NPTS * 3)    pts   = (const float*)d_in[i];
        else if (in_sizes[i] == NB * NH * 4) ypred = (const float*)d_in[i];
        else if (in_sizes[i] == 1)           thr   = (const int*)d_in[i];
    }
    float* out = (float*)d_out;

    plane_validator_kernel<<<NBLOCKS, THREADS>>>(pts, ypred, thr, out);
}